// round 14
// baseline (speedup 1.0000x reference)
#include <cuda_runtime.h>
#include <math.h>

// ---------------------------------------------------------------------------
// Improved_DSTGAT_Attn_Adaptive — R13
//  k1: unchanged (R11)
//  k_gat: R11 512-thread version (R12's 1024-thr tiling reverted: it doubled
//         smem traffic) + PDL: prologue (weights + lM build) overlaps k1 tail,
//         cudaGridDependencySynchronize() before reading g_feats.
// ---------------------------------------------------------------------------

#define NSEQ 8192
#define TLEN 500
#define HS   512
typedef unsigned long long ull;

__device__ float g_feats[NSEQ * 16];
__device__ float g_ps1[128 * 32];
__device__ float g_ps2[128 * 32];
__device__ unsigned int g_syncc[2];

__device__ __forceinline__ float elu1(float x) {
    float e = __expf(x) - 1.f;
    return x > 0.f ? x : e;
}
__device__ __forceinline__ float geluf(float x) { return 0.5f * x * (1.f + erff(x * 0.70710678118654752f)); }
__device__ __forceinline__ float sigm(float x)  { return 1.f / (1.f + __expf(-x)); }

__device__ __forceinline__ ull pk(float lo, float hi) {
    ull r; asm("mov.b64 %0, {%1,%2};" : "=l"(r) : "f"(lo), "f"(hi)); return r;
}
__device__ __forceinline__ float2 upk(ull v) {
    float2 r; asm("mov.b64 {%0,%1}, %2;" : "=f"(r.x), "=f"(r.y) : "l"(v)); return r;
}
__device__ __forceinline__ ull dup2(float x) {
    ull r; asm("mov.b64 %0, {%1,%1};" : "=l"(r) : "f"(x)); return r;
}
__device__ __forceinline__ ull f2fma(ull a, ull b, ull c) {
    ull d; asm("fma.rn.f32x2 %0, %1, %2, %3;" : "=l"(d) : "l"(a), "l"(b), "l"(c)); return d;
}

// Device-wide barrier: all 128 blocks co-resident (1 block/SM).
__device__ __forceinline__ void gbar(volatile unsigned int* c)
{
    __syncthreads();
    if (threadIdx.x == 0) {
        __threadfence();
        atomicAdd((unsigned int*)c, 1u);
        while (*c < 128u) { __nanosleep(64); }
    }
    __syncthreads();
    __threadfence();
}

// ---------------------------------------------------------------------------
// K1: fused feature extractor (R11, unchanged)
// ---------------------------------------------------------------------------
__global__ __launch_bounds__(256, 3) void k1_feat(
    const float* __restrict__ x,
    const float* __restrict__ c1w,  const float* __restrict__ bn1,
    const float* __restrict__ dww,  const float* __restrict__ bn2,
    const float* __restrict__ sdww, const float* __restrict__ spww,
    const float* __restrict__ bn3)
{
    extern __shared__ float sm[];
    ull* c1pS = (ull*)sm;           // 208
    ull* c1bS = c1pS + 208;         // 8
    ull* dwpS = c1bS + 8;           // 24
    ull* dwbS = dwpS + 24;          // 8
    ull* sdpS = dwbS + 8;           // 24
    ull* pwS  = sdpS + 24;          // 256
    float* xs = sm + 1056;          // 528
    float* hA = xs + 528;           // 16*512
    float* hB = hA + 16 * HS;       // 16*512

    int tid = threadIdx.x, warp = tid >> 5, lane = tid & 31;
    int seq = blockIdx.x;
    const float* xp = x + (size_t)seq * TLEN;

    if (tid < 125) {
        float4 v = *(const float4*)(xp + tid * 4);
        *(float4*)&xs[12 + tid * 4] = v;
    } else if (tid < 128) {
        int q = tid - 125;
        *(float4*)&xs[q * 4] = make_float4(0.f, 0.f, 0.f, 0.f);
    } else if (tid < 132) {
        int q = tid - 128;
        *(float4*)&xs[512 + q * 4] = make_float4(0.f, 0.f, 0.f, 0.f);
    } else if (tid < 148) {
        int c = tid - 132;
        float4 z = {0.f, 0.f, 0.f, 0.f};
        *(float4*)&hA[c * HS]       = z;
        *(float4*)&hA[c * HS + 504] = z;
        *(float4*)&hA[c * HS + 508] = z;
    }

    int f0 = warp * 2, f1 = f0 + 1;

    float sc0 = bn1[f0] * rsqrtf(bn1[48 + f0] + 1e-5f);
    float sc1 = bn1[f1] * rsqrtf(bn1[48 + f1] + 1e-5f);
    float b0  = bn1[16 + f0] - bn1[32 + f0] * sc0;
    float b1  = bn1[16 + f1] - bn1[32 + f1] * sc1;
    float dsc0 = bn2[f0] * rsqrtf(bn2[48 + f0] + 1e-5f);
    float dsc1 = bn2[f1] * rsqrtf(bn2[48 + f1] + 1e-5f);
    float db0  = bn2[16 + f0] - bn2[32 + f0] * dsc0;
    float db1  = bn2[16 + f1] - bn2[32 + f1] * dsc1;
    float psc0 = bn3[f0] * rsqrtf(bn3[48 + f0] + 1e-5f);
    float psc1 = bn3[f1] * rsqrtf(bn3[48 + f1] + 1e-5f);
    float pb0  = bn3[16 + f0] - bn3[32 + f0] * psc0;
    float pb1  = bn3[16 + f1] - bn3[32 + f1] * psc1;

    if (lane < 25)       c1pS[warp * 26 + lane] = pk(c1w[f0 * 25 + lane] * sc0, c1w[f1 * 25 + lane] * sc1);
    else if (lane == 25) c1bS[warp] = pk(b0, b1);
    else if (lane == 26) dwbS[warp] = pk(db0, db1);
    else if (lane < 30) { int k = lane - 27; dwpS[warp * 3 + k] = pk(dww[f0 * 3 + k] * dsc0, dww[f1 * 3 + k] * dsc1); }
    if (lane < 3)  sdpS[warp * 3 + lane] = pk(sdww[f0 * 3 + lane], sdww[f1 * 3 + lane]);
    if (lane < 16) {
        pwS[warp * 32 + lane * 2]     = dup2(spww[f0 * 16 + lane] * psc0);
        pwS[warp * 32 + lane * 2 + 1] = dup2(spww[f1 * 16 + lane] * psc1);
    }
    __syncthreads();

    // conv1 K=25 + BN + ELU -> hA[ch][t+4]
    {
        ull cb = c1bS[warp];
        for (int p = lane; p < 125; p += 32) {
            const float4* xq = ((const float4*)xs) + p;
            float xw[28];
            #pragma unroll
            for (int q = 0; q < 7; q++) {
                float4 v = xq[q];
                xw[4*q] = v.x; xw[4*q+1] = v.y; xw[4*q+2] = v.z; xw[4*q+3] = v.w;
            }
            ull a0 = cb, a1 = cb, a2 = cb, a3 = cb;
            ull r0 = dup2(xw[0]), r1 = dup2(xw[1]), r2 = dup2(xw[2]);
            #pragma unroll
            for (int k = 0; k < 24; k += 2) {
                ulonglong2 wp = *(const ulonglong2*)&c1pS[warp * 26 + k];
                ull r3 = dup2(xw[k + 3]);
                a0 = f2fma(r0, wp.x, a0);
                a1 = f2fma(r1, wp.x, a1);
                a2 = f2fma(r2, wp.x, a2);
                a3 = f2fma(r3, wp.x, a3);
                ull r4 = dup2(xw[k + 4]);
                a0 = f2fma(r1, wp.y, a0);
                a1 = f2fma(r2, wp.y, a1);
                a2 = f2fma(r3, wp.y, a2);
                a3 = f2fma(r4, wp.y, a3);
                r0 = r2; r1 = r3; r2 = r4;
            }
            {
                ull wk = c1pS[warp * 26 + 24];
                ull r3 = dup2(xw[27]);
                a0 = f2fma(r0, wk, a0);
                a1 = f2fma(r1, wk, a1);
                a2 = f2fma(r2, wk, a2);
                a3 = f2fma(r3, wk, a3);
            }
            float2 v0 = upk(a0), v1 = upk(a1), v2 = upk(a2), v3 = upk(a3);
            float4 A0 = {elu1(v0.x), elu1(v1.x), elu1(v2.x), elu1(v3.x)};
            float4 A1 = {elu1(v0.y), elu1(v1.y), elu1(v2.y), elu1(v3.y)};
            *(float4*)&hA[f0 * HS + 4*p + 4] = A0;
            *(float4*)&hA[f1 * HS + 4*p + 4] = A1;
        }
    }
    __syncwarp();

    // fused dw K=3 (BN+ELU) + sdw K=3 -> hB
    {
        ull db = dwbS[warp];
        ull d0 = dwpS[warp * 3 + 0], d1 = dwpS[warp * 3 + 1], d2 = dwpS[warp * 3 + 2];
        ull e0 = sdpS[warp * 3 + 0], e1 = sdpS[warp * 3 + 1], e2 = sdpS[warp * 3 + 2];
        for (int p = lane; p < 125; p += 32) {
            const float* A0 = &hA[f0 * HS + 4*p];
            const float* A1 = &hA[f1 * HS + 4*p];
            float4 q00 = *(const float4*)A0, q01 = *(const float4*)(A0 + 4), q02 = *(const float4*)(A0 + 8);
            float4 q10 = *(const float4*)A1, q11 = *(const float4*)(A1 + 4), q12 = *(const float4*)(A1 + 8);
            ull cc[8];
            cc[0] = pk(q00.z, q10.z); cc[1] = pk(q00.w, q10.w);
            cc[2] = pk(q01.x, q11.x); cc[3] = pk(q01.y, q11.y);
            cc[4] = pk(q01.z, q11.z); cc[5] = pk(q01.w, q11.w);
            cc[6] = pk(q02.x, q12.x); cc[7] = pk(q02.y, q12.y);
            ull ev[6];
            #pragma unroll
            for (int u = 0; u < 6; u++) {
                ull t = f2fma(cc[u], d0, f2fma(cc[u+1], d1, f2fma(cc[u+2], d2, db)));
                float2 w = upk(t);
                ev[u] = pk(elu1(w.x), elu1(w.y));
            }
            if (p == 0)   ev[0] = 0ull;
            if (p == 124) ev[5] = 0ull;
            float2 o0, o1, o2, o3;
            {
                ull z = 0ull;
                o0 = upk(f2fma(ev[0], e0, f2fma(ev[1], e1, f2fma(ev[2], e2, z))));
                o1 = upk(f2fma(ev[1], e0, f2fma(ev[2], e1, f2fma(ev[3], e2, z))));
                o2 = upk(f2fma(ev[2], e0, f2fma(ev[3], e1, f2fma(ev[4], e2, z))));
                o3 = upk(f2fma(ev[3], e0, f2fma(ev[4], e1, f2fma(ev[5], e2, z))));
            }
            float4 B0 = {o0.x, o1.x, o2.x, o3.x};
            float4 B1 = {o0.y, o1.y, o2.y, o3.y};
            *(float4*)&hB[f0 * HS + 4*p] = B0;
            *(float4*)&hB[f1 * HS + 4*p] = B1;
        }
    }
    __syncthreads();

    // pointwise 16->16 + BN + ELU + temporal mean
    {
        float s0 = 0.f, s1 = 0.f;
        for (int p = lane; p < 125; p += 32) {
            ull a01_0 = dup2(pb0), a23_0 = dup2(pb0);
            ull a01_1 = dup2(pb1), a23_1 = dup2(pb1);
            #pragma unroll
            for (int c = 0; c < 16; c++) {
                ulonglong2 xv = *(const ulonglong2*)&hB[c * HS + 4*p];
                ulonglong2 wv = *(const ulonglong2*)&pwS[warp * 32 + c * 2];
                a01_0 = f2fma(xv.x, wv.x, a01_0);
                a23_0 = f2fma(xv.y, wv.x, a23_0);
                a01_1 = f2fma(xv.x, wv.y, a01_1);
                a23_1 = f2fma(xv.y, wv.y, a23_1);
            }
            float2 u;
            u = upk(a01_0); s0 += elu1(u.x) + elu1(u.y);
            u = upk(a23_0); s0 += elu1(u.x) + elu1(u.y);
            u = upk(a01_1); s1 += elu1(u.x) + elu1(u.y);
            u = upk(a23_1); s1 += elu1(u.x) + elu1(u.y);
        }
        #pragma unroll
        for (int o = 16; o > 0; o >>= 1) {
            s0 += __shfl_xor_sync(0xffffffffu, s0, o);
            s1 += __shfl_xor_sync(0xffffffffu, s1, o);
        }
        if (lane == 0) {
            g_feats[seq * 16 + f0] = s0 * (1.f / 500.f);
            g_feats[seq * 16 + f1] = s1 * (1.f / 500.f);
        }
    }
}

// ---------------------------------------------------------------------------
// GAT attention pass 1 (512 thr)
// ---------------------------------------------------------------------------
__device__ __forceinline__ void gat_alpha(const float* sv, const float* dv,
                                          const float* lM, float* al, int tid)
{
    int ih = tid >> 1, half = tid & 1;
    int i = ih >> 2, h = ih & 3;
    int j0 = half << 5;
    float di = dv[i * 4 + h];
    float e[32];
    float mx = -1e30f;
    #pragma unroll
    for (int jj = 0; jj < 32; jj++) {
        float t = di + sv[(j0 + jj) * 4 + h];
        e[jj] = (t > 0.f ? t : 0.2f * t) + lM[i * 64 + j0 + jj];
        mx = fmaxf(mx, e[jj]);
    }
    mx = fmaxf(mx, __shfl_xor_sync(0xffffffffu, mx, 1));
    float den = 0.f;
    #pragma unroll
    for (int jj = 0; jj < 32; jj++) {
        e[jj] = __expf(e[jj] - mx);
        den += e[jj];
    }
    den += __shfl_xor_sync(0xffffffffu, den, 1);
    float inv = 1.f / den;
    float* ap = &al[(h * 64 + i) * 68 + j0];
    #pragma unroll
    for (int jj = 0; jj < 32; jj += 4) {
        float4 w4 = {e[jj] * inv, e[jj+1] * inv, e[jj+2] * inv, e[jj+3] * inv};
        *(float4*)&ap[jj] = w4;
    }
}

// ---------------------------------------------------------------------------
// GAT attention pass 2 (512 thr, 4i x 4f tile, f32x2)
// ---------------------------------------------------------------------------
__device__ __forceinline__ void gat_aggr(const float* xls, const float* al,
                                         float* ho, int tid)
{
    int ig = tid >> 5, h = (tid >> 3) & 3, fq = tid & 7;
    int i0 = ig * 4;
    ull acc[4][2];
    #pragma unroll
    for (int i = 0; i < 4; i++) { acc[i][0] = 0ull; acc[i][1] = 0ull; }
    const float* xbase = &xls[h * 36 + fq * 4];
    const float* abase = &al[(h * 64 + i0) * 68];
    #pragma unroll 4
    for (int jc = 0; jc < 16; jc++) {
        const float* xb = xbase + (4 * jc) * 148;
        ulonglong2 x0 = *(const ulonglong2*)xb;
        ulonglong2 x1 = *(const ulonglong2*)(xb + 148);
        ulonglong2 x2 = *(const ulonglong2*)(xb + 296);
        ulonglong2 x3 = *(const ulonglong2*)(xb + 444);
        const float* ab = abase + jc * 4;
        float4 a0 = *(const float4*)ab;
        float4 a1 = *(const float4*)(ab + 68);
        float4 a2 = *(const float4*)(ab + 136);
        float4 a3 = *(const float4*)(ab + 204);
        #define AGG(ai, av) { \
            ull s0 = dup2(av.x), s1 = dup2(av.y), s2 = dup2(av.z), s3 = dup2(av.w); \
            acc[ai][0] = f2fma(s0, x0.x, acc[ai][0]); acc[ai][1] = f2fma(s0, x0.y, acc[ai][1]); \
            acc[ai][0] = f2fma(s1, x1.x, acc[ai][0]); acc[ai][1] = f2fma(s1, x1.y, acc[ai][1]); \
            acc[ai][0] = f2fma(s2, x2.x, acc[ai][0]); acc[ai][1] = f2fma(s2, x2.y, acc[ai][1]); \
            acc[ai][0] = f2fma(s3, x3.x, acc[ai][0]); acc[ai][1] = f2fma(s3, x3.y, acc[ai][1]); }
        AGG(0, a0) AGG(1, a1) AGG(2, a2) AGG(3, a3)
        #undef AGG
    }
    #pragma unroll
    for (int i = 0; i < 4; i++) {
        float2 lo = upk(acc[i][0]), hi = upk(acc[i][1]);
        float4 v = {lo.x, lo.y, hi.x, hi.y};
        *(float4*)&ho[(i0 + i) * 148 + h * 36 + fq * 4] = v;
    }
}

// xl matmul (512 thr, 4j x 4col, f32x2) fused with sv/dv partials.
template<int C>
__device__ __forceinline__ void gat_matmul(const float* src, const float* Ws,
                                           const float* asr, const float* ads,
                                           float* xls, float* sv, float* dv, int tid)
{
    int jq = tid >> 5, colq = tid & 31;
    int j0 = jq * 4;
    int hh = colq >> 3, fq = colq & 7, ff = fq * 4;
    ull a0[2] = {0,0}, a1[2] = {0,0}, a2[2] = {0,0}, a3[2] = {0,0};
    #pragma unroll
    for (int cq = 0; cq < C / 4; cq++) {
        float4 x0 = *(const float4*)&src[(j0 + 0) * C + cq * 4];
        float4 x1 = *(const float4*)&src[(j0 + 1) * C + cq * 4];
        float4 x2 = *(const float4*)&src[(j0 + 2) * C + cq * 4];
        float4 x3 = *(const float4*)&src[(j0 + 3) * C + cq * 4];
        #pragma unroll
        for (int c4 = 0; c4 < 4; c4++) {
            ulonglong2 w = *(const ulonglong2*)&Ws[(cq * 4 + c4) * 128 + colq * 4];
            ull s0 = dup2(((const float*)&x0)[c4]);
            ull s1 = dup2(((const float*)&x1)[c4]);
            ull s2 = dup2(((const float*)&x2)[c4]);
            ull s3 = dup2(((const float*)&x3)[c4]);
            a0[0] = f2fma(s0, w.x, a0[0]); a0[1] = f2fma(s0, w.y, a0[1]);
            a1[0] = f2fma(s1, w.x, a1[0]); a1[1] = f2fma(s1, w.y, a1[1]);
            a2[0] = f2fma(s2, w.x, a2[0]); a2[1] = f2fma(s2, w.y, a2[1]);
            a3[0] = f2fma(s3, w.x, a3[0]); a3[1] = f2fma(s3, w.y, a3[1]);
        }
    }
    float4 av = *(const float4*)&asr[hh * 32 + ff];
    float4 aw = *(const float4*)&ads[hh * 32 + ff];
    float sj[4], dj[4];
    float4 vv[4];
    float2 l, h2;
    l = upk(a0[0]); h2 = upk(a0[1]); vv[0] = make_float4(l.x, l.y, h2.x, h2.y);
    l = upk(a1[0]); h2 = upk(a1[1]); vv[1] = make_float4(l.x, l.y, h2.x, h2.y);
    l = upk(a2[0]); h2 = upk(a2[1]); vv[2] = make_float4(l.x, l.y, h2.x, h2.y);
    l = upk(a3[0]); h2 = upk(a3[1]); vv[3] = make_float4(l.x, l.y, h2.x, h2.y);
    #pragma unroll
    for (int i = 0; i < 4; i++) {
        *(float4*)&xls[(j0 + i) * 148 + hh * 36 + ff] = vv[i];
        sj[i] = vv[i].x * av.x + vv[i].y * av.y + vv[i].z * av.z + vv[i].w * av.w;
        dj[i] = vv[i].x * aw.x + vv[i].y * aw.y + vv[i].z * aw.z + vv[i].w * aw.w;
    }
    #pragma unroll
    for (int o = 1; o < 8; o <<= 1) {
        #pragma unroll
        for (int i = 0; i < 4; i++) {
            sj[i] += __shfl_xor_sync(0xffffffffu, sj[i], o);
            dj[i] += __shfl_xor_sync(0xffffffffu, dj[i], o);
        }
    }
    if (fq == 0) {
        #pragma unroll
        for (int i = 0; i < 4; i++) {
            sv[(j0 + i) * 4 + hh] = sj[i];
            dv[(j0 + i) * 4 + hh] = dj[i];
        }
    }
}

// ---------------------------------------------------------------------------
// Merged persistent GAT kernel (128 blocks x 512 thr) with PDL prologue
// ---------------------------------------------------------------------------
__global__ __launch_bounds__(512) void k_gat(
    const float* __restrict__ g1w,  const float* __restrict__ g1as,
    const float* __restrict__ g1ad, const float* __restrict__ g1b,
    const float* __restrict__ bng1, const float* __restrict__ skw,
    const float* __restrict__ g2w,  const float* __restrict__ g2as,
    const float* __restrict__ g2ad, const float* __restrict__ g2b,
    const float* __restrict__ bng2, const float* __restrict__ se1a,
    const float* __restrict__ se1b, const float* __restrict__ se2a,
    const float* __restrict__ se2b, const float* __restrict__ clfw,
    const float* __restrict__ clfb, const float* __restrict__ nemb,
    const int*   __restrict__ ei,   float* __restrict__ out)
{
    extern __shared__ float sm[];
    float* xin = sm;              // 2048 (Es scratch in prologue)
    float* Ws  = xin + 2048;      // 4096
    float* xls = Ws + 4096;       // 9472 (Ms int scratch in prologue)
    float* al  = xls + 9472;      // 17408
    float* ho  = al + 17408;      // 9472 (As scratch / gate-sum scratch)
    float* sv  = ho + 9472;       // 256
    float* dv  = sv + 256;        // 256
    float* asr = dv + 256;        // 128
    float* ads = asr + 128;       // 128
    float* lM  = ads + 128;       // 4096
    float* vt  = lM + 4096;       // 2048
    float* gate = vt + 2048;      // 72
    float* bnS = gate + 72;       // 160
    float* fs  = bnS + 160;       // 1024
    float* skT = fs + 1024;       // 512
    float* denS = skT + 512;      // 64
    float* ps2o = denS + 64;      // 32
    float* seS = ps2o + 32;       // 1090
    int tid = threadIdx.x;
    int b = blockIdx.x;

    // ---- PDL prologue: everything independent of g_feats ----
    if (tid < 512) *(float4*)&Ws[tid * 4] = *(const float4*)&g1w[tid * 4];
    if (tid < 128) { asr[tid] = g1as[tid]; ads[tid] = g1ad[tid]; }
    {
        int f = tid >> 4, c = tid & 15;
        skT[c * 32 + f] = skw[tid];
    }
    if (tid < 32) bnS[tid] = g1b[tid];
    if (tid >= 128 && tid < 256) bnS[32 + (tid - 128)] = bng1[tid - 128];
    if (tid >= 256 && tid < 512) seS[tid - 256] = se1a[tid - 256];
    if (tid < 256) seS[256 + tid] = se1b[tid];
    if (tid >= 256 && tid < 512) seS[512 + (tid - 256)] = se2a[tid - 256];
    if (tid < 256) seS[768 + tid] = se2b[tid];
    if (tid >= 448 && tid < 512) seS[1024 + (tid - 448)] = clfw[tid - 448];
    if (tid == 447) { seS[1088] = clfb[0]; seS[1089] = clfb[1]; }
    for (int i = tid; i < 1024; i += 512) xin[i] = nemb[i];   // Es
    int* MsI = (int*)xls;
    for (int i = tid; i < 4096; i += 512) MsI[i] = 0;
    __syncthreads();

    for (int idx = tid; idx < 4096; idx += 512) {             // As = relu(E E^T)
        int i = idx >> 6, j = idx & 63;
        float a = 0.f;
        #pragma unroll
        for (int c = 0; c < 16; c++) a += xin[i * 16 + c] * xin[j * 16 + c];
        ho[i * 65 + j] = a > 0.f ? a : 0.f;
    }
    __syncthreads();
    if (tid < 64) {
        float s = 0.f;
        for (int j = 0; j < 64; j++) s += ho[tid * 65 + j];
        denS[tid] = s + 1e-6f;
    }
    if (tid >= 64 && tid < 320) {
        int q = tid - 64;
        atomicAdd(&MsI[ei[q] * 64 + ei[256 + q]], 1);
    }
    __syncthreads();
    for (int idx = tid; idx < 4096; idx += 512) {
        int i = idx >> 6, j = idx & 63;
        float dyn = (ho[i * 65 + j] > 0.1f * denS[i]) ? 1.f : 0.f;
        float Mv  = (i == j) ? 1.f : ((float)MsI[idx] + dyn);
        lM[idx] = (Mv > 0.f) ? __logf(Mv) : -1e30f;
    }

    // ---- wait for k1 (PDL), then load this block's feats ----
    cudaGridDependencySynchronize();
    for (int i = tid; i < 256; i += 512)
        *(float4*)&fs[i * 4] = *(const float4*)&g_feats[b * 1024 + i * 4];
    __syncthreads();

    // ---- phase A: GAT layer 1 ----
    gat_matmul<16>(fs, Ws, asr, ads, xls, sv, dv, tid);
    __syncthreads();
    gat_alpha(sv, dv, lM, al, tid);
    __syncthreads();
    gat_aggr(xls, al, ho, tid);
    __syncthreads();

    for (int idx = tid; idx < 2048; idx += 512) {
        int i = idx >> 5, f = idx & 31;
        const float* hr = &ho[i * 148 + f];
        float o = 0.25f * (hr[0] + hr[36] + hr[72] + hr[108]) + bnS[f];
        float sc = bnS[32 + f] * rsqrtf(bnS[32 + 96 + f] + 1e-5f);
        o = (o - bnS[32 + 64 + f]) * sc + bnS[32 + 32 + f];
        float sk = 0.f;
        #pragma unroll
        for (int c = 0; c < 16; c++) sk += fs[i * 16 + c] * skT[c * 32 + f];
        vt[idx] = geluf(o + sk);
    }
    __syncthreads();
    if (tid < 32) {
        float s = 0.f;
        for (int i = 0; i < 64; i++) s += vt[i * 32 + tid];
        g_ps1[b * 32 + tid] = s;
        __threadfence();
    }
    // stage layer-2 weights (overlaps the grid barrier)
    for (int i = tid; i < 1024; i += 512)
        *(float4*)&Ws[i * 4] = *(const float4*)&g2w[i * 4];
    if (tid < 128) { asr[tid] = g2as[tid]; ads[tid] = g2ad[tid]; }
    if (tid < 32) bnS[tid] = g2b[tid];
    if (tid >= 128 && tid < 256) bnS[32 + (tid - 128)] = bng2[tid - 128];

    gbar(&g_syncc[0]);

    // ---- SE gate 1 ----
    {
        int f = tid & 31, g = tid >> 5;
        float s = 0.f;
        #pragma unroll
        for (int q = 0; q < 8; q++) s += g_ps1[(g * 8 + q) * 32 + f];
        ho[g * 32 + f] = s;
    }
    __syncthreads();
    if (tid < 32) {
        float s = 0.f;
        #pragma unroll
        for (int g = 0; g < 16; g++) s += ho[g * 32 + tid];
        gate[tid] = s * (1.f / 8192.f);
    }
    __syncthreads();
    if (tid < 8) {
        float a = 0.f;
        #pragma unroll
        for (int c = 0; c < 32; c++) a += gate[c] * seS[tid * 32 + c];
        gate[32 + tid] = fmaxf(a, 0.f);
    }
    __syncthreads();
    if (tid < 32) {
        float a = 0.f;
        #pragma unroll
        for (int r = 0; r < 8; r++) a += gate[32 + r] * seS[256 + tid * 8 + r];
        gate[40 + tid] = sigm(a);
    }
    __syncthreads();

    for (int idx = tid; idx < 2048; idx += 512)
        xin[idx] = vt[idx] * gate[40 + (idx & 31)];
    __syncthreads();

    // ---- phase B: GAT layer 2 ----
    gat_matmul<32>(xin, Ws, asr, ads, xls, sv, dv, tid);
    __syncthreads();
    gat_alpha(sv, dv, lM, al, tid);
    __syncthreads();
    gat_aggr(xls, al, ho, tid);
    __syncthreads();

    for (int idx = tid; idx < 2048; idx += 512) {
        int i = idx >> 5, f = idx & 31;
        const float* hr = &ho[i * 148 + f];
        float o = 0.25f * (hr[0] + hr[36] + hr[72] + hr[108]) + bnS[f];
        float sc = bnS[32 + f] * rsqrtf(bnS[32 + 96 + f] + 1e-5f);
        o = (o - bnS[32 + 64 + f]) * sc + bnS[32 + 32 + f];
        vt[idx] = geluf(o + xin[idx]);
    }
    __syncthreads();
    if (tid < 32) {
        float s = 0.f;
        for (int i = 0; i < 64; i++) s += vt[i * 32 + tid];
        g_ps2[b * 32 + tid] = s;
        ps2o[tid] = s;
        __threadfence();
    }

    gbar(&g_syncc[1]);

    // ---- phase C: SE gate 2 + pool + classifier ----
    {
        int f = tid & 31, g = tid >> 5;
        float s = 0.f;
        #pragma unroll
        for (int q = 0; q < 8; q++) s += g_ps2[(g * 8 + q) * 32 + f];
        ho[g * 32 + f] = s;
    }
    __syncthreads();
    if (tid < 32) {
        float s = 0.f;
        #pragma unroll
        for (int g = 0; g < 16; g++) s += ho[g * 32 + tid];
        gate[tid] = s * (1.f / 8192.f);
    }
    __syncthreads();
    if (tid < 8) {
        float a = 0.f;
        #pragma unroll
        for (int c = 0; c < 32; c++) a += gate[c] * seS[512 + tid * 32 + c];
        gate[32 + tid] = fmaxf(a, 0.f);
    }
    __syncthreads();
    if (tid < 32) {
        float a = 0.f;
        #pragma unroll
        for (int r = 0; r < 8; r++) a += gate[32 + r] * seS[768 + tid * 8 + r];
        float gg = sigm(a);
        float pooled = ps2o[tid] * (1.f / 64.f) * gg;
        float r0 = pooled * seS[1024 + tid];
        float r1 = pooled * seS[1024 + 32 + tid];
        #pragma unroll
        for (int o = 16; o > 0; o >>= 1) {
            r0 += __shfl_xor_sync(0xffffffffu, r0, o);
            r1 += __shfl_xor_sync(0xffffffffu, r1, o);
        }
        if (tid == 0) {
            out[b * 2 + 0] = r0 + seS[1088];
            out[b * 2 + 1] = r1 + seS[1089];
        }
    }
}

// ---------------------------------------------------------------------------
extern "C" void kernel_launch(void* const* d_in, const int* in_sizes, int n_in,
                              void* d_out, int out_size)
{
    const float* x    = (const float*)d_in[0];
    const int*   ei   = (const int*)  d_in[1];
    const float* c1w  = (const float*)d_in[2];
    const float* bn1  = (const float*)d_in[3];
    const float* dww  = (const float*)d_in[4];
    const float* bn2  = (const float*)d_in[5];
    const float* sdww = (const float*)d_in[6];
    const float* spww = (const float*)d_in[7];
    const float* bn3  = (const float*)d_in[8];
    const float* nemb = (const float*)d_in[9];
    const float* g1w  = (const float*)d_in[10];
    const float* g1as = (const float*)d_in[11];
    const float* g1ad = (const float*)d_in[12];
    const float* g1b  = (const float*)d_in[13];
    const float* bng1 = (const float*)d_in[14];
    const float* sk1  = (const float*)d_in[15];
    const float* se1a = (const float*)d_in[16];
    const float* se1b = (const float*)d_in[17];
    const float* g2w  = (const float*)d_in[18];
    const float* g2as = (const float*)d_in[19];
    const float* g2ad = (const float*)d_in[20];
    const float* g2b  = (const float*)d_in[21];
    const float* bng2 = (const float*)d_in[22];
    const float* se2a = (const float*)d_in[23];
    const float* se2b = (const float*)d_in[24];
    const float* clfw = (const float*)d_in[25];
    const float* clfb = (const float*)d_in[26];
    float* out = (float*)d_out;

    const int SM1 = 17968 * 4;   // 71,872 B
    const int SMG = 52362 * 4;   // 209,448 B
    cudaFuncSetAttribute(k1_feat, cudaFuncAttributeMaxDynamicSharedMemorySize, SM1);
    cudaFuncSetAttribute(k_gat,  cudaFuncAttributeMaxDynamicSharedMemorySize, SMG);

    void* syncp = nullptr;
    cudaGetSymbolAddress(&syncp, g_syncc);
    cudaMemsetAsync(syncp, 0, 2 * sizeof(unsigned int), 0);

    k1_feat<<<NSEQ, 256, SM1>>>(x, c1w, bn1, dww, bn2, sdww, spww, bn3);

    // k_gat with programmatic dependent launch: prologue overlaps k1 tail.
    cudaLaunchAttribute attrs[1];
    attrs[0].id = cudaLaunchAttributeProgrammaticStreamSerialization;
    attrs[0].val.programmaticStreamSerializationAllowed = 1;
    cudaLaunchConfig_t cfg = {};
    cfg.gridDim = dim3(128, 1, 1);
    cfg.blockDim = dim3(512, 1, 1);
    cfg.dynamicSmemBytes = SMG;
    cfg.stream = 0;
    cfg.attrs = attrs;
    cfg.numAttrs = 1;
    cudaLaunchKernelEx(&cfg, k_gat,
                       g1w, g1as, g1ad, g1b, bng1, sk1,
                       g2w, g2as, g2ad, g2b, bng2, se1a, se1b,
                       se2a, se2b, clfw, clfb, nemb, ei, out);
}

// round 15
// speedup vs baseline: 1.0558x; 1.0558x over previous
#include <cuda_runtime.h>
#include <math.h>

// ---------------------------------------------------------------------------
// Improved_DSTGAT_Attn_Adaptive — R15
//  = R11 (best measured, 241.7us) + divide-free prologue threshold.
//  PDL from R13/R14 reverted: dependent blocks displaced k1's tail CTAs.
// ---------------------------------------------------------------------------

#define NSEQ 8192
#define TLEN 500
#define HS   512
typedef unsigned long long ull;

__device__ float g_feats[NSEQ * 16];
__device__ float g_ps1[128 * 32];
__device__ float g_ps2[128 * 32];
__device__ unsigned int g_syncc[2];

__device__ __forceinline__ float elu1(float x) {
    float e = __expf(x) - 1.f;
    return x > 0.f ? x : e;
}
__device__ __forceinline__ float geluf(float x) { return 0.5f * x * (1.f + erff(x * 0.70710678118654752f)); }
__device__ __forceinline__ float sigm(float x)  { return 1.f / (1.f + __expf(-x)); }

__device__ __forceinline__ ull pk(float lo, float hi) {
    ull r; asm("mov.b64 %0, {%1,%2};" : "=l"(r) : "f"(lo), "f"(hi)); return r;
}
__device__ __forceinline__ float2 upk(ull v) {
    float2 r; asm("mov.b64 {%0,%1}, %2;" : "=f"(r.x), "=f"(r.y) : "l"(v)); return r;
}
__device__ __forceinline__ ull dup2(float x) {
    ull r; asm("mov.b64 %0, {%1,%1};" : "=l"(r) : "f"(x)); return r;
}
__device__ __forceinline__ ull f2fma(ull a, ull b, ull c) {
    ull d; asm("fma.rn.f32x2 %0, %1, %2, %3;" : "=l"(d) : "l"(a), "l"(b), "l"(c)); return d;
}

// Device-wide barrier: all 128 blocks co-resident (1 block/SM).
__device__ __forceinline__ void gbar(volatile unsigned int* c)
{
    __syncthreads();
    if (threadIdx.x == 0) {
        __threadfence();
        atomicAdd((unsigned int*)c, 1u);
        while (*c < 128u) { __nanosleep(64); }
    }
    __syncthreads();
    __threadfence();
}

// ---------------------------------------------------------------------------
// K1: fused feature extractor (R11, unchanged)
// ---------------------------------------------------------------------------
__global__ __launch_bounds__(256, 3) void k1_feat(
    const float* __restrict__ x,
    const float* __restrict__ c1w,  const float* __restrict__ bn1,
    const float* __restrict__ dww,  const float* __restrict__ bn2,
    const float* __restrict__ sdww, const float* __restrict__ spww,
    const float* __restrict__ bn3)
{
    extern __shared__ float sm[];
    ull* c1pS = (ull*)sm;           // 208
    ull* c1bS = c1pS + 208;         // 8
    ull* dwpS = c1bS + 8;           // 24
    ull* dwbS = dwpS + 24;          // 8
    ull* sdpS = dwbS + 8;           // 24
    ull* pwS  = sdpS + 24;          // 256
    float* xs = sm + 1056;          // 528
    float* hA = xs + 528;           // 16*512
    float* hB = hA + 16 * HS;       // 16*512

    int tid = threadIdx.x, warp = tid >> 5, lane = tid & 31;
    int seq = blockIdx.x;
    const float* xp = x + (size_t)seq * TLEN;

    if (tid < 125) {
        float4 v = *(const float4*)(xp + tid * 4);
        *(float4*)&xs[12 + tid * 4] = v;
    } else if (tid < 128) {
        int q = tid - 125;
        *(float4*)&xs[q * 4] = make_float4(0.f, 0.f, 0.f, 0.f);
    } else if (tid < 132) {
        int q = tid - 128;
        *(float4*)&xs[512 + q * 4] = make_float4(0.f, 0.f, 0.f, 0.f);
    } else if (tid < 148) {
        int c = tid - 132;
        float4 z = {0.f, 0.f, 0.f, 0.f};
        *(float4*)&hA[c * HS]       = z;
        *(float4*)&hA[c * HS + 504] = z;
        *(float4*)&hA[c * HS + 508] = z;
    }

    int f0 = warp * 2, f1 = f0 + 1;

    float sc0 = bn1[f0] * rsqrtf(bn1[48 + f0] + 1e-5f);
    float sc1 = bn1[f1] * rsqrtf(bn1[48 + f1] + 1e-5f);
    float b0  = bn1[16 + f0] - bn1[32 + f0] * sc0;
    float b1  = bn1[16 + f1] - bn1[32 + f1] * sc1;
    float dsc0 = bn2[f0] * rsqrtf(bn2[48 + f0] + 1e-5f);
    float dsc1 = bn2[f1] * rsqrtf(bn2[48 + f1] + 1e-5f);
    float db0  = bn2[16 + f0] - bn2[32 + f0] * dsc0;
    float db1  = bn2[16 + f1] - bn2[32 + f1] * dsc1;
    float psc0 = bn3[f0] * rsqrtf(bn3[48 + f0] + 1e-5f);
    float psc1 = bn3[f1] * rsqrtf(bn3[48 + f1] + 1e-5f);
    float pb0  = bn3[16 + f0] - bn3[32 + f0] * psc0;
    float pb1  = bn3[16 + f1] - bn3[32 + f1] * psc1;

    if (lane < 25)       c1pS[warp * 26 + lane] = pk(c1w[f0 * 25 + lane] * sc0, c1w[f1 * 25 + lane] * sc1);
    else if (lane == 25) c1bS[warp] = pk(b0, b1);
    else if (lane == 26) dwbS[warp] = pk(db0, db1);
    else if (lane < 30) { int k = lane - 27; dwpS[warp * 3 + k] = pk(dww[f0 * 3 + k] * dsc0, dww[f1 * 3 + k] * dsc1); }
    if (lane < 3)  sdpS[warp * 3 + lane] = pk(sdww[f0 * 3 + lane], sdww[f1 * 3 + lane]);
    if (lane < 16) {
        pwS[warp * 32 + lane * 2]     = dup2(spww[f0 * 16 + lane] * psc0);
        pwS[warp * 32 + lane * 2 + 1] = dup2(spww[f1 * 16 + lane] * psc1);
    }
    __syncthreads();

    // conv1 K=25 + BN + ELU -> hA[ch][t+4]
    {
        ull cb = c1bS[warp];
        for (int p = lane; p < 125; p += 32) {
            const float4* xq = ((const float4*)xs) + p;
            float xw[28];
            #pragma unroll
            for (int q = 0; q < 7; q++) {
                float4 v = xq[q];
                xw[4*q] = v.x; xw[4*q+1] = v.y; xw[4*q+2] = v.z; xw[4*q+3] = v.w;
            }
            ull a0 = cb, a1 = cb, a2 = cb, a3 = cb;
            ull r0 = dup2(xw[0]), r1 = dup2(xw[1]), r2 = dup2(xw[2]);
            #pragma unroll
            for (int k = 0; k < 24; k += 2) {
                ulonglong2 wp = *(const ulonglong2*)&c1pS[warp * 26 + k];
                ull r3 = dup2(xw[k + 3]);
                a0 = f2fma(r0, wp.x, a0);
                a1 = f2fma(r1, wp.x, a1);
                a2 = f2fma(r2, wp.x, a2);
                a3 = f2fma(r3, wp.x, a3);
                ull r4 = dup2(xw[k + 4]);
                a0 = f2fma(r1, wp.y, a0);
                a1 = f2fma(r2, wp.y, a1);
                a2 = f2fma(r3, wp.y, a2);
                a3 = f2fma(r4, wp.y, a3);
                r0 = r2; r1 = r3; r2 = r4;
            }
            {
                ull wk = c1pS[warp * 26 + 24];
                ull r3 = dup2(xw[27]);
                a0 = f2fma(r0, wk, a0);
                a1 = f2fma(r1, wk, a1);
                a2 = f2fma(r2, wk, a2);
                a3 = f2fma(r3, wk, a3);
            }
            float2 v0 = upk(a0), v1 = upk(a1), v2 = upk(a2), v3 = upk(a3);
            float4 A0 = {elu1(v0.x), elu1(v1.x), elu1(v2.x), elu1(v3.x)};
            float4 A1 = {elu1(v0.y), elu1(v1.y), elu1(v2.y), elu1(v3.y)};
            *(float4*)&hA[f0 * HS + 4*p + 4] = A0;
            *(float4*)&hA[f1 * HS + 4*p + 4] = A1;
        }
    }
    __syncwarp();

    // fused dw K=3 (BN+ELU) + sdw K=3 -> hB
    {
        ull db = dwbS[warp];
        ull d0 = dwpS[warp * 3 + 0], d1 = dwpS[warp * 3 + 1], d2 = dwpS[warp * 3 + 2];
        ull e0 = sdpS[warp * 3 + 0], e1 = sdpS[warp * 3 + 1], e2 = sdpS[warp * 3 + 2];
        for (int p = lane; p < 125; p += 32) {
            const float* A0 = &hA[f0 * HS + 4*p];
            const float* A1 = &hA[f1 * HS + 4*p];
            float4 q00 = *(const float4*)A0, q01 = *(const float4*)(A0 + 4), q02 = *(const float4*)(A0 + 8);
            float4 q10 = *(const float4*)A1, q11 = *(const float4*)(A1 + 4), q12 = *(const float4*)(A1 + 8);
            ull cc[8];
            cc[0] = pk(q00.z, q10.z); cc[1] = pk(q00.w, q10.w);
            cc[2] = pk(q01.x, q11.x); cc[3] = pk(q01.y, q11.y);
            cc[4] = pk(q01.z, q11.z); cc[5] = pk(q01.w, q11.w);
            cc[6] = pk(q02.x, q12.x); cc[7] = pk(q02.y, q12.y);
            ull ev[6];
            #pragma unroll
            for (int u = 0; u < 6; u++) {
                ull t = f2fma(cc[u], d0, f2fma(cc[u+1], d1, f2fma(cc[u+2], d2, db)));
                float2 w = upk(t);
                ev[u] = pk(elu1(w.x), elu1(w.y));
            }
            if (p == 0)   ev[0] = 0ull;
            if (p == 124) ev[5] = 0ull;
            float2 o0, o1, o2, o3;
            {
                ull z = 0ull;
                o0 = upk(f2fma(ev[0], e0, f2fma(ev[1], e1, f2fma(ev[2], e2, z))));
                o1 = upk(f2fma(ev[1], e0, f2fma(ev[2], e1, f2fma(ev[3], e2, z))));
                o2 = upk(f2fma(ev[2], e0, f2fma(ev[3], e1, f2fma(ev[4], e2, z))));
                o3 = upk(f2fma(ev[3], e0, f2fma(ev[4], e1, f2fma(ev[5], e2, z))));
            }
            float4 B0 = {o0.x, o1.x, o2.x, o3.x};
            float4 B1 = {o0.y, o1.y, o2.y, o3.y};
            *(float4*)&hB[f0 * HS + 4*p] = B0;
            *(float4*)&hB[f1 * HS + 4*p] = B1;
        }
    }
    __syncthreads();

    // pointwise 16->16 + BN + ELU + temporal mean
    {
        float s0 = 0.f, s1 = 0.f;
        for (int p = lane; p < 125; p += 32) {
            ull a01_0 = dup2(pb0), a23_0 = dup2(pb0);
            ull a01_1 = dup2(pb1), a23_1 = dup2(pb1);
            #pragma unroll
            for (int c = 0; c < 16; c++) {
                ulonglong2 xv = *(const ulonglong2*)&hB[c * HS + 4*p];
                ulonglong2 wv = *(const ulonglong2*)&pwS[warp * 32 + c * 2];
                a01_0 = f2fma(xv.x, wv.x, a01_0);
                a23_0 = f2fma(xv.y, wv.x, a23_0);
                a01_1 = f2fma(xv.x, wv.y, a01_1);
                a23_1 = f2fma(xv.y, wv.y, a23_1);
            }
            float2 u;
            u = upk(a01_0); s0 += elu1(u.x) + elu1(u.y);
            u = upk(a23_0); s0 += elu1(u.x) + elu1(u.y);
            u = upk(a01_1); s1 += elu1(u.x) + elu1(u.y);
            u = upk(a23_1); s1 += elu1(u.x) + elu1(u.y);
        }
        #pragma unroll
        for (int o = 16; o > 0; o >>= 1) {
            s0 += __shfl_xor_sync(0xffffffffu, s0, o);
            s1 += __shfl_xor_sync(0xffffffffu, s1, o);
        }
        if (lane == 0) {
            g_feats[seq * 16 + f0] = s0 * (1.f / 500.f);
            g_feats[seq * 16 + f1] = s1 * (1.f / 500.f);
        }
    }
}

// ---------------------------------------------------------------------------
// GAT attention pass 1 (512 thr)
// ---------------------------------------------------------------------------
__device__ __forceinline__ void gat_alpha(const float* sv, const float* dv,
                                          const float* lM, float* al, int tid)
{
    int ih = tid >> 1, half = tid & 1;
    int i = ih >> 2, h = ih & 3;
    int j0 = half << 5;
    float di = dv[i * 4 + h];
    float e[32];
    float mx = -1e30f;
    #pragma unroll
    for (int jj = 0; jj < 32; jj++) {
        float t = di + sv[(j0 + jj) * 4 + h];
        e[jj] = (t > 0.f ? t : 0.2f * t) + lM[i * 64 + j0 + jj];
        mx = fmaxf(mx, e[jj]);
    }
    mx = fmaxf(mx, __shfl_xor_sync(0xffffffffu, mx, 1));
    float den = 0.f;
    #pragma unroll
    for (int jj = 0; jj < 32; jj++) {
        e[jj] = __expf(e[jj] - mx);
        den += e[jj];
    }
    den += __shfl_xor_sync(0xffffffffu, den, 1);
    float inv = 1.f / den;
    float* ap = &al[(h * 64 + i) * 68 + j0];
    #pragma unroll
    for (int jj = 0; jj < 32; jj += 4) {
        float4 w4 = {e[jj] * inv, e[jj+1] * inv, e[jj+2] * inv, e[jj+3] * inv};
        *(float4*)&ap[jj] = w4;
    }
}

// ---------------------------------------------------------------------------
// GAT attention pass 2 (512 thr, 4i x 4f tile, f32x2)
// ---------------------------------------------------------------------------
__device__ __forceinline__ void gat_aggr(const float* xls, const float* al,
                                         float* ho, int tid)
{
    int ig = tid >> 5, h = (tid >> 3) & 3, fq = tid & 7;
    int i0 = ig * 4;
    ull acc[4][2];
    #pragma unroll
    for (int i = 0; i < 4; i++) { acc[i][0] = 0ull; acc[i][1] = 0ull; }
    const float* xbase = &xls[h * 36 + fq * 4];
    const float* abase = &al[(h * 64 + i0) * 68];
    #pragma unroll 4
    for (int jc = 0; jc < 16; jc++) {
        const float* xb = xbase + (4 * jc) * 148;
        ulonglong2 x0 = *(const ulonglong2*)xb;
        ulonglong2 x1 = *(const ulonglong2*)(xb + 148);
        ulonglong2 x2 = *(const ulonglong2*)(xb + 296);
        ulonglong2 x3 = *(const ulonglong2*)(xb + 444);
        const float* ab = abase + jc * 4;
        float4 a0 = *(const float4*)ab;
        float4 a1 = *(const float4*)(ab + 68);
        float4 a2 = *(const float4*)(ab + 136);
        float4 a3 = *(const float4*)(ab + 204);
        #define AGG(ai, av) { \
            ull s0 = dup2(av.x), s1 = dup2(av.y), s2 = dup2(av.z), s3 = dup2(av.w); \
            acc[ai][0] = f2fma(s0, x0.x, acc[ai][0]); acc[ai][1] = f2fma(s0, x0.y, acc[ai][1]); \
            acc[ai][0] = f2fma(s1, x1.x, acc[ai][0]); acc[ai][1] = f2fma(s1, x1.y, acc[ai][1]); \
            acc[ai][0] = f2fma(s2, x2.x, acc[ai][0]); acc[ai][1] = f2fma(s2, x2.y, acc[ai][1]); \
            acc[ai][0] = f2fma(s3, x3.x, acc[ai][0]); acc[ai][1] = f2fma(s3, x3.y, acc[ai][1]); }
        AGG(0, a0) AGG(1, a1) AGG(2, a2) AGG(3, a3)
        #undef AGG
    }
    #pragma unroll
    for (int i = 0; i < 4; i++) {
        float2 lo = upk(acc[i][0]), hi = upk(acc[i][1]);
        float4 v = {lo.x, lo.y, hi.x, hi.y};
        *(float4*)&ho[(i0 + i) * 148 + h * 36 + fq * 4] = v;
    }
}

// xl matmul (512 thr, 4j x 4col, f32x2) fused with sv/dv partials.
template<int C>
__device__ __forceinline__ void gat_matmul(const float* src, const float* Ws,
                                           const float* asr, const float* ads,
                                           float* xls, float* sv, float* dv, int tid)
{
    int jq = tid >> 5, colq = tid & 31;
    int j0 = jq * 4;
    int hh = colq >> 3, fq = colq & 7, ff = fq * 4;
    ull a0[2] = {0,0}, a1[2] = {0,0}, a2[2] = {0,0}, a3[2] = {0,0};
    #pragma unroll
    for (int cq = 0; cq < C / 4; cq++) {
        float4 x0 = *(const float4*)&src[(j0 + 0) * C + cq * 4];
        float4 x1 = *(const float4*)&src[(j0 + 1) * C + cq * 4];
        float4 x2 = *(const float4*)&src[(j0 + 2) * C + cq * 4];
        float4 x3 = *(const float4*)&src[(j0 + 3) * C + cq * 4];
        #pragma unroll
        for (int c4 = 0; c4 < 4; c4++) {
            ulonglong2 w = *(const ulonglong2*)&Ws[(cq * 4 + c4) * 128 + colq * 4];
            ull s0 = dup2(((const float*)&x0)[c4]);
            ull s1 = dup2(((const float*)&x1)[c4]);
            ull s2 = dup2(((const float*)&x2)[c4]);
            ull s3 = dup2(((const float*)&x3)[c4]);
            a0[0] = f2fma(s0, w.x, a0[0]); a0[1] = f2fma(s0, w.y, a0[1]);
            a1[0] = f2fma(s1, w.x, a1[0]); a1[1] = f2fma(s1, w.y, a1[1]);
            a2[0] = f2fma(s2, w.x, a2[0]); a2[1] = f2fma(s2, w.y, a2[1]);
            a3[0] = f2fma(s3, w.x, a3[0]); a3[1] = f2fma(s3, w.y, a3[1]);
        }
    }
    float4 av = *(const float4*)&asr[hh * 32 + ff];
    float4 aw = *(const float4*)&ads[hh * 32 + ff];
    float sj[4], dj[4];
    float4 vv[4];
    float2 l, h2;
    l = upk(a0[0]); h2 = upk(a0[1]); vv[0] = make_float4(l.x, l.y, h2.x, h2.y);
    l = upk(a1[0]); h2 = upk(a1[1]); vv[1] = make_float4(l.x, l.y, h2.x, h2.y);
    l = upk(a2[0]); h2 = upk(a2[1]); vv[2] = make_float4(l.x, l.y, h2.x, h2.y);
    l = upk(a3[0]); h2 = upk(a3[1]); vv[3] = make_float4(l.x, l.y, h2.x, h2.y);
    #pragma unroll
    for (int i = 0; i < 4; i++) {
        *(float4*)&xls[(j0 + i) * 148 + hh * 36 + ff] = vv[i];
        sj[i] = vv[i].x * av.x + vv[i].y * av.y + vv[i].z * av.z + vv[i].w * av.w;
        dj[i] = vv[i].x * aw.x + vv[i].y * aw.y + vv[i].z * aw.z + vv[i].w * aw.w;
    }
    #pragma unroll
    for (int o = 1; o < 8; o <<= 1) {
        #pragma unroll
        for (int i = 0; i < 4; i++) {
            sj[i] += __shfl_xor_sync(0xffffffffu, sj[i], o);
            dj[i] += __shfl_xor_sync(0xffffffffu, dj[i], o);
        }
    }
    if (fq == 0) {
        #pragma unroll
        for (int i = 0; i < 4; i++) {
            sv[(j0 + i) * 4 + hh] = sj[i];
            dv[(j0 + i) * 4 + hh] = dj[i];
        }
    }
}

// ---------------------------------------------------------------------------
// Merged persistent GAT kernel (128 blocks x 512 thr)
// ---------------------------------------------------------------------------
__global__ __launch_bounds__(512) void k_gat(
    const float* __restrict__ g1w,  const float* __restrict__ g1as,
    const float* __restrict__ g1ad, const float* __restrict__ g1b,
    const float* __restrict__ bng1, const float* __restrict__ skw,
    const float* __restrict__ g2w,  const float* __restrict__ g2as,
    const float* __restrict__ g2ad, const float* __restrict__ g2b,
    const float* __restrict__ bng2, const float* __restrict__ se1a,
    const float* __restrict__ se1b, const float* __restrict__ se2a,
    const float* __restrict__ se2b, const float* __restrict__ clfw,
    const float* __restrict__ clfb, const float* __restrict__ nemb,
    const int*   __restrict__ ei,   float* __restrict__ out)
{
    extern __shared__ float sm[];
    float* xin = sm;              // 2048 (Es scratch in prologue)
    float* Ws  = xin + 2048;      // 4096
    float* xls = Ws + 4096;       // 9472 (Ms int scratch in prologue)
    float* al  = xls + 9472;      // 17408
    float* ho  = al + 17408;      // 9472 (As scratch / gate-sum scratch)
    float* sv  = ho + 9472;       // 256
    float* dv  = sv + 256;        // 256
    float* asr = dv + 256;        // 128
    float* ads = asr + 128;       // 128
    float* lM  = ads + 128;       // 4096
    float* vt  = lM + 4096;       // 2048
    float* gate = vt + 2048;      // 72
    float* bnS = gate + 72;       // 160
    float* fs  = bnS + 160;       // 1024
    float* skT = fs + 1024;       // 512
    float* denS = skT + 512;      // 64
    float* ps2o = denS + 64;      // 32
    float* seS = ps2o + 32;       // 1090
    int tid = threadIdx.x;
    int b = blockIdx.x;

    // ---- prologue: stage everything + build lM ----
    for (int i = tid; i < 256; i += 512)
        *(float4*)&fs[i * 4] = *(const float4*)&g_feats[b * 1024 + i * 4];
    *(float4*)&Ws[tid * 4] = *(const float4*)&g1w[tid * 4];
    if (tid < 128) { asr[tid] = g1as[tid]; ads[tid] = g1ad[tid]; }
    {
        int f = tid >> 4, c = tid & 15;
        skT[c * 32 + f] = skw[tid];
    }
    if (tid < 32) bnS[tid] = g1b[tid];
    if (tid >= 128 && tid < 256) bnS[32 + (tid - 128)] = bng1[tid - 128];
    if (tid >= 256 && tid < 512) seS[tid - 256] = se1a[tid - 256];
    if (tid < 256) seS[256 + tid] = se1b[tid];
    if (tid >= 256 && tid < 512) seS[512 + (tid - 256)] = se2a[tid - 256];
    if (tid < 256) seS[768 + tid] = se2b[tid];
    if (tid >= 448 && tid < 512) seS[1024 + (tid - 448)] = clfw[tid - 448];
    if (tid == 447) { seS[1088] = clfb[0]; seS[1089] = clfb[1]; }
    for (int i = tid; i < 1024; i += 512) xin[i] = nemb[i];   // Es
    int* MsI = (int*)xls;
    for (int i = tid; i < 4096; i += 512) MsI[i] = 0;
    __syncthreads();

    for (int idx = tid; idx < 4096; idx += 512) {             // As = relu(E E^T)
        int i = idx >> 6, j = idx & 63;
        float a = 0.f;
        #pragma unroll
        for (int c = 0; c < 16; c++) a += xin[i * 16 + c] * xin[j * 16 + c];
        ho[i * 65 + j] = a > 0.f ? a : 0.f;
    }
    __syncthreads();
    if (tid < 64) {
        float s = 0.f;
        for (int j = 0; j < 64; j++) s += ho[tid * 65 + j];
        denS[tid] = s + 1e-6f;
    }
    if (tid >= 64 && tid < 320) {
        int q = tid - 64;
        atomicAdd(&MsI[ei[q] * 64 + ei[256 + q]], 1);
    }
    __syncthreads();
    for (int idx = tid; idx < 4096; idx += 512) {
        int i = idx >> 6, j = idx & 63;
        float dyn = (ho[i * 65 + j] > 0.1f * denS[i]) ? 1.f : 0.f;
        float Mv  = (i == j) ? 1.f : ((float)MsI[idx] + dyn);
        lM[idx] = (Mv > 0.f) ? __logf(Mv) : -1e30f;
    }
    __syncthreads();

    // ---- phase A: GAT layer 1 ----
    gat_matmul<16>(fs, Ws, asr, ads, xls, sv, dv, tid);
    __syncthreads();
    gat_alpha(sv, dv, lM, al, tid);
    __syncthreads();
    gat_aggr(xls, al, ho, tid);
    __syncthreads();

    for (int idx = tid; idx < 2048; idx += 512) {
        int i = idx >> 5, f = idx & 31;
        const float* hr = &ho[i * 148 + f];
        float o = 0.25f * (hr[0] + hr[36] + hr[72] + hr[108]) + bnS[f];
        float sc = bnS[32 + f] * rsqrtf(bnS[32 + 96 + f] + 1e-5f);
        o = (o - bnS[32 + 64 + f]) * sc + bnS[32 + 32 + f];
        float sk = 0.f;
        #pragma unroll
        for (int c = 0; c < 16; c++) sk += fs[i * 16 + c] * skT[c * 32 + f];
        vt[idx] = geluf(o + sk);
    }
    __syncthreads();
    if (tid < 32) {
        float s = 0.f;
        for (int i = 0; i < 64; i++) s += vt[i * 32 + tid];
        g_ps1[b * 32 + tid] = s;
        __threadfence();
    }
    // stage layer-2 weights (overlaps the grid barrier)
    for (int i = tid; i < 1024; i += 512)
        *(float4*)&Ws[i * 4] = *(const float4*)&g2w[i * 4];
    if (tid < 128) { asr[tid] = g2as[tid]; ads[tid] = g2ad[tid]; }
    if (tid < 32) bnS[tid] = g2b[tid];
    if (tid >= 128 && tid < 256) bnS[32 + (tid - 128)] = bng2[tid - 128];

    gbar(&g_syncc[0]);

    // ---- SE gate 1 ----
    {
        int f = tid & 31, g = tid >> 5;
        float s = 0.f;
        #pragma unroll
        for (int q = 0; q < 8; q++) s += g_ps1[(g * 8 + q) * 32 + f];
        ho[g * 32 + f] = s;
    }
    __syncthreads();
    if (tid < 32) {
        float s = 0.f;
        #pragma unroll
        for (int g = 0; g < 16; g++) s += ho[g * 32 + tid];
        gate[tid] = s * (1.f / 8192.f);
    }
    __syncthreads();
    if (tid < 8) {
        float a = 0.f;
        #pragma unroll
        for (int c = 0; c < 32; c++) a += gate[c] * seS[tid * 32 + c];
        gate[32 + tid] = fmaxf(a, 0.f);
    }
    __syncthreads();
    if (tid < 32) {
        float a = 0.f;
        #pragma unroll
        for (int r = 0; r < 8; r++) a += gate[32 + r] * seS[256 + tid * 8 + r];
        gate[40 + tid] = sigm(a);
    }
    __syncthreads();

    for (int idx = tid; idx < 2048; idx += 512)
        xin[idx] = vt[idx] * gate[40 + (idx & 31)];
    __syncthreads();

    // ---- phase B: GAT layer 2 ----
    gat_matmul<32>(xin, Ws, asr, ads, xls, sv, dv, tid);
    __syncthreads();
    gat_alpha(sv, dv, lM, al, tid);
    __syncthreads();
    gat_aggr(xls, al, ho, tid);
    __syncthreads();

    for (int idx = tid; idx < 2048; idx += 512) {
        int i = idx >> 5, f = idx & 31;
        const float* hr = &ho[i * 148 + f];
        float o = 0.25f * (hr[0] + hr[36] + hr[72] + hr[108]) + bnS[f];
        float sc = bnS[32 + f] * rsqrtf(bnS[32 + 96 + f] + 1e-5f);
        o = (o - bnS[32 + 64 + f]) * sc + bnS[32 + 32 + f];
        vt[idx] = geluf(o + xin[idx]);
    }
    __syncthreads();
    if (tid < 32) {
        float s = 0.f;
        for (int i = 0; i < 64; i++) s += vt[i * 32 + tid];
        g_ps2[b * 32 + tid] = s;
        ps2o[tid] = s;
        __threadfence();
    }

    gbar(&g_syncc[1]);

    // ---- phase C: SE gate 2 + pool + classifier ----
    {
        int f = tid & 31, g = tid >> 5;
        float s = 0.f;
        #pragma unroll
        for (int q = 0; q < 8; q++) s += g_ps2[(g * 8 + q) * 32 + f];
        ho[g * 32 + f] = s;
    }
    __syncthreads();
    if (tid < 32) {
        float s = 0.f;
        #pragma unroll
        for (int g = 0; g < 16; g++) s += ho[g * 32 + tid];
        gate[tid] = s * (1.f / 8192.f);
    }
    __syncthreads();
    if (tid < 8) {
        float a = 0.f;
        #pragma unroll
        for (int c = 0; c < 32; c++) a += gate[c] * seS[512 + tid * 32 + c];
        gate[32 + tid] = fmaxf(a, 0.f);
    }
    __syncthreads();
    if (tid < 32) {
        float a = 0.f;
        #pragma unroll
        for (int r = 0; r < 8; r++) a += gate[32 + r] * seS[768 + tid * 8 + r];
        float gg = sigm(a);
        float pooled = ps2o[tid] * (1.f / 64.f) * gg;
        float r0 = pooled * seS[1024 + tid];
        float r1 = pooled * seS[1024 + 32 + tid];
        #pragma unroll
        for (int o = 16; o > 0; o >>= 1) {
            r0 += __shfl_xor_sync(0xffffffffu, r0, o);
            r1 += __shfl_xor_sync(0xffffffffu, r1, o);
        }
        if (tid == 0) {
            out[b * 2 + 0] = r0 + seS[1088];
            out[b * 2 + 1] = r1 + seS[1089];
        }
    }
}

// ---------------------------------------------------------------------------
extern "C" void kernel_launch(void* const* d_in, const int* in_sizes, int n_in,
                              void* d_out, int out_size)
{
    const float* x    = (const float*)d_in[0];
    const int*   ei   = (const int*)  d_in[1];
    const float* c1w  = (const float*)d_in[2];
    const float* bn1  = (const float*)d_in[3];
    const float* dww  = (const float*)d_in[4];
    const float* bn2  = (const float*)d_in[5];
    const float* sdww = (const float*)d_in[6];
    const float* spww = (const float*)d_in[7];
    const float* bn3  = (const float*)d_in[8];
    const float* nemb = (const float*)d_in[9];
    const float* g1w  = (const float*)d_in[10];
    const float* g1as = (const float*)d_in[11];
    const float* g1ad = (const float*)d_in[12];
    const float* g1b  = (const float*)d_in[13];
    const float* bng1 = (const float*)d_in[14];
    const float* sk1  = (const float*)d_in[15];
    const float* se1a = (const float*)d_in[16];
    const float* se1b = (const float*)d_in[17];
    const float* g2w  = (const float*)d_in[18];
    const float* g2as = (const float*)d_in[19];
    const float* g2ad = (const float*)d_in[20];
    const float* g2b  = (const float*)d_in[21];
    const float* bng2 = (const float*)d_in[22];
    const float* se2a = (const float*)d_in[23];
    const float* se2b = (const float*)d_in[24];
    const float* clfw = (const float*)d_in[25];
    const float* clfb = (const float*)d_in[26];
    float* out = (float*)d_out;

    const int SM1 = 17968 * 4;   // 71,872 B
    const int SMG = 52362 * 4;   // 209,448 B
    cudaFuncSetAttribute(k1_feat, cudaFuncAttributeMaxDynamicSharedMemorySize, SM1);
    cudaFuncSetAttribute(k_gat,  cudaFuncAttributeMaxDynamicSharedMemorySize, SMG);

    void* syncp = nullptr;
    cudaGetSymbolAddress(&syncp, g_syncc);
    cudaMemsetAsync(syncp, 0, 2 * sizeof(unsigned int), 0);

    k1_feat<<<NSEQ, 256, SM1>>>(x, c1w, bn1, dww, bn2, sdww, spww, bn3);
    k_gat<<<128, 512, SMG>>>(g1w, g1as, g1ad, g1b, bng1, sk1,
                             g2w, g2as, g2ad, g2b, bng2, se1a, se1b,
                             se2a, se2b, clfw, clfb, nemb, ei, out);
}